// round 14
// baseline (speedup 1.0000x reference)
#include <cuda_runtime.h>
#include <cstdint>

#define BATCH 32
#define CIN   256
#define COUT  256
#define HH_   56
#define WW_   56
#define HW_   (HH_*WW_)
#define NPOS  (BATCH*HW_)

// ---------------- device scratch ----------------
__device__ uint4 g_xpack[NPOS * 2];        // [pos][2]: 8 u32 sign bits (bit=1 iff x>=0)
__device__ uint4 g_wpack[COUT * 9 * 2];    // [cout*9+tap][2]

// ---------------- fused pack kernel ----------------
__global__ void pack_all_kernel(const float* __restrict__ x,
                                const float* __restrict__ wgt) {
    if (blockIdx.x < 392) {                       // 392*256 == NPOS exactly
        int pos = blockIdx.x * 256 + threadIdx.x;
        int b  = pos / HW_;
        int hw = pos - b * HW_;
        const float* xp = x + (size_t)b * CIN * HW_ + hw;
        uint32_t wds[8];
        #pragma unroll
        for (int k = 0; k < 8; ++k) {
            uint32_t wd = 0;
            #pragma unroll
            for (int i = 0; i < 32; ++i) {
                float v = xp[(size_t)(k * 32 + i) * HW_];
                wd |= (v >= 0.0f ? 1u : 0u) << i;
            }
            wds[k] = wd;
        }
        g_xpack[pos * 2 + 0] = make_uint4(wds[0], wds[1], wds[2], wds[3]);
        g_xpack[pos * 2 + 1] = make_uint4(wds[4], wds[5], wds[6], wds[7]);
    } else {
        int idx = (blockIdx.x - 392) * 256 + threadIdx.x;   // cout*9+tap
        if (idx >= COUT * 9) return;
        int cout = idx / 9;
        int tap  = idx - cout * 9;
        const float* wp = wgt + (size_t)cout * CIN * 9 + tap;
        uint32_t wds[8];
        #pragma unroll
        for (int k = 0; k < 8; ++k) {
            uint32_t wd = 0;
            #pragma unroll
            for (int i = 0; i < 32; ++i) {
                float v = wp[(size_t)(k * 32 + i) * 9];
                wd |= (v >= 0.0f ? 1u : 0u) << i;
            }
            wds[k] = wd;
        }
        g_wpack[idx * 2 + 0] = make_uint4(wds[0], wds[1], wds[2], wds[3]);
        g_wpack[idx * 2 + 1] = make_uint4(wds[4], wds[5], wds[6], wds[7]);
    }
}

// ---------------- main conv: EIGHTH cin split, high occupancy ----------------
// Block = 256 threads = 8 warps. Lane = grp*4 + csub.
//   csub (0..3) -> cout = bz*32 + wid*4 + csub
//   grp  (0..7) -> cin word grp (32 channels)
// Block computes one (b, h) output row for 32 couts.
__global__ void __launch_bounds__(256, 6)
bconv_pop_kernel(const float* __restrict__ bias, float* __restrict__ out) {
    __shared__ uint32_t xs[3 * WW_ * 8];     // [row][v][word]

    const int tid  = threadIdx.x;
    const int lane = tid & 31;
    const int wid  = tid >> 5;
    const int grp  = lane >> 2;
    const int csub = lane & 3;
    const int h    = blockIdx.x;
    const int b    = blockIdx.y;
    const int cout = blockIdx.z * 32 + wid * 4 + csub;

    const bool rv0 = (h > 0), rv2 = (h < HH_ - 1);

    // ---- stage x (3 rows x 56 cols x 8 words), zero-fill invalid rows ----
    {
        const uint32_t* gx = (const uint32_t*)g_xpack;
        for (int i = tid; i < 3 * WW_ * 8; i += 256) {
            int row = i / (WW_ * 8);
            int rem = i - row * (WW_ * 8);
            int rin = h - 1 + row;
            uint32_t val = 0u;
            if (rin >= 0 && rin < HH_)
                val = gx[((size_t)(b * HH_ + rin) * WW_) * 8 + rem];
            xs[i] = val;
        }
    }

    // ---- per-lane word-weights in registers (9 regs) ----
    uint32_t wreg[9];
    {
        const uint32_t* gw = (const uint32_t*)g_wpack;
        #pragma unroll
        for (int t = 0; t < 9; ++t)
            wreg[t] = gw[(cout * 9 + t) * 8 + grp];
    }
    const float bv = bias[cout];

    // ---- per-grp pad-correction constants (32 channels each) ----
    int cmid, cleft, cright;
    {
        int pm0 = __popc(wreg[0]) + __popc(wreg[1]) + __popc(wreg[2]);
        int pm2 = __popc(wreg[6]) + __popc(wreg[7]) + __popc(wreg[8]);
        int pl0 = __popc(wreg[1]) + __popc(wreg[2]);
        int pl2 = __popc(wreg[7]) + __popc(wreg[8]);
        int pr0 = __popc(wreg[0]) + __popc(wreg[1]);
        int pr2 = __popc(wreg[6]) + __popc(wreg[7]);
        const int nrows = (int)rv0 + 1 + (int)rv2;
        cmid   = 96 * nrows + 2 * ((rv0 ? 0 : pm0) + (rv2 ? 0 : pm2));
        cleft  = 64 * nrows + 2 * ((rv0 ? 0 : pl0) + (rv2 ? 0 : pl2));
        cright = 64 * nrows + 2 * ((rv0 ? 0 : pr0) + (rv2 ? 0 : pr2));
    }

    __syncthreads();

    float* obase = out + ((size_t)(b * COUT + cout) * HH_ + h) * WW_;

    int ring[4] = {0, 0, 0, 0};
    float fb0 = 0.0f;

    // v = input column. x col v feeds outputs w = v+1-dw, dw in {0,1,2}.
    // Output w completes at end of step v = w+1.
    for (int v0 = 0; v0 < 7; ++v0) {
        #pragma unroll
        for (int u = 0; u < 8; ++u) {
            const int v = v0 * 8 + u;
            uint32_t x0 = xs[(0 * WW_ + v) * 8 + grp];
            uint32_t x1 = xs[(1 * WW_ + v) * 8 + grp];
            uint32_t x2 = xs[(2 * WW_ + v) * 8 + grp];

            int addn = __popc(x0 ^ wreg[0]) + __popc(x1 ^ wreg[3]) + __popc(x2 ^ wreg[6]);
            int addm = __popc(x0 ^ wreg[1]) + __popc(x1 ^ wreg[4]) + __popc(x2 ^ wreg[7]);
            int addo = __popc(x0 ^ wreg[2]) + __popc(x1 ^ wreg[5]) + __popc(x2 ^ wreg[8]);

            ring[(u + 1) & 3] += addn;      // w = v+1
            ring[u & 3]       += addm;      // w = v
            ring[(u + 3) & 3] += addo;      // w = v-1 (completes now)

            if (u == 0) {
                if (v0 == 0) {
                    ring[3] = 0;            // discard w=-1 garbage
                } else {
                    // w = 8*v0 - 1 (odd) -> pair store
                    int comb = cmid - 2 * ring[3];
                    comb += __shfl_xor_sync(0xffffffffu, comb, 4);
                    comb += __shfl_xor_sync(0xffffffffu, comb, 8);
                    comb += __shfl_xor_sync(0xffffffffu, comb, 16);
                    ring[3] = 0;
                    if (grp == 0)
                        *(float2*)(obase + v0 * 8 - 2) =
                            make_float2(fb0, (float)comb + bv);
                }
            } else {
                const int slot = (u + 3) & 3;
                int c = cmid;
                if (u == 1) c = (v0 == 0) ? cleft : cmid;   // w==0 edge
                int comb = c - 2 * ring[slot];
                comb += __shfl_xor_sync(0xffffffffu, comb, 4);
                comb += __shfl_xor_sync(0xffffffffu, comb, 8);
                comb += __shfl_xor_sync(0xffffffffu, comb, 16);
                ring[slot] = 0;
                if (u & 1) {
                    fb0 = (float)comb + bv;               // w even -> stash
                } else if (grp == 0) {
                    *(float2*)(obase + v0 * 8 + u - 2) =  // w odd -> pair store
                        make_float2(fb0, (float)comb + bv);
                }
            }
        }
    }
    // tail: w = 55 (odd, edge) sits in slot 3; fb0 holds w=54
    {
        int comb = cright - 2 * ring[3];
        comb += __shfl_xor_sync(0xffffffffu, comb, 4);
        comb += __shfl_xor_sync(0xffffffffu, comb, 8);
        comb += __shfl_xor_sync(0xffffffffu, comb, 16);
        if (grp == 0)
            *(float2*)(obase + 54) = make_float2(fb0, (float)comb + bv);
    }
}

// ---------------------------------------------------------------------------
extern "C" void kernel_launch(void* const* d_in, const int* in_sizes, int n_in,
                              void* d_out, int out_size) {
    const float* x    = (const float*)d_in[0];
    const float* wgt  = (const float*)d_in[1];
    const float* bias = (const float*)d_in[2];
    float* out = (float*)d_out;

    pack_all_kernel<<<401, 256>>>(x, wgt);
    dim3 grid(HH_, BATCH, 8);
    bconv_pop_kernel<<<grid, 256>>>(bias, out);
}